// round 16
// baseline (speedup 1.0000x reference)
#include <cuda_runtime.h>
#include <cstdint>

// Phase 1: bucket edges by dst (CAP/node), 8 edges/thread (MLP=8).
// Phase 2: warp-per-node gather-reduce with SPECULATIVE index prefetch:
//          first 4 bucket indices per half load unconditionally (in-bounds by
//          construction) in parallel with the g_cnt load, gathers predicated
//          -> removes one ~250cyc L2 link from the per-warp critical path.
//          4 accumulators cover deg<=16 (most nodes) in one memory stage.

#define D_FEAT 64
#define CHUNKS 16
#define CAP 64            // Poisson(12.5): P(deg>64) ~ 1e-24 per node
#define BU 8              // edges per bucket thread

#define MAX_NODES 131072
#define MAX_EDGES 2097152
#define MAX_OVF   4096

__device__ int g_cnt[MAX_NODES + 1];   // [n_nodes] = overflow counter; zero-init
__device__ int g_elist[MAX_NODES * CAP];
__device__ int2 g_ovf[MAX_OVF];        // (src, dst)

// ---------------- build buckets, 8 edges/thread ----------------

__global__ void bucket_kernel(const int* __restrict__ src,
                              const int* __restrict__ dst,
                              int n_edges, int n_nodes, int Q)
{
    int t = blockIdx.x * blockDim.x + threadIdx.x;
    if (t >= Q) return;

    int s[BU], d[BU], ok[BU];
#pragma unroll
    for (int k = 0; k < BU; k++) {
        int e = t + k * Q;
        ok[k] = (e < n_edges);
        if (ok[k]) {
            s[k] = __ldg(src + e);
            d[k] = __ldg(dst + e);
            if ((unsigned)s[k] >= (unsigned)n_nodes ||
                (unsigned)d[k] >= (unsigned)n_nodes) ok[k] = 0;
        }
    }

    int pos[BU];
#pragma unroll
    for (int k = 0; k < BU; k++)
        if (ok[k]) pos[k] = atomicAdd(&g_cnt[d[k]], 1);

#pragma unroll
    for (int k = 0; k < BU; k++) {
        if (!ok[k]) continue;
        if (pos[k] < CAP) {
            g_elist[(size_t)d[k] * CAP + pos[k]] = s[k];
        } else {
            int op = atomicAdd(&g_cnt[n_nodes], 1);
            if (op < MAX_OVF) g_ovf[op] = make_int2(s[k], d[k]);
        }
    }
}

// ---------------- warp-per-node gather-reduce ----------------
// lane = 2 halves (edge-parallel) x 16 chunks. Half h handles edges
// e = h, h+2, h+4, ... First 4 edges per half: indices prefetched
// unconditionally, gathers predicated. Tail: simple 2-wide loop.

__global__ void aggregate_kernel(const float4* __restrict__ x4,
                                 float4* __restrict__ out4,
                                 int n_nodes)
{
    int warp = (blockIdx.x * blockDim.x + threadIdx.x) >> 5;
    if (warp >= n_nodes) return;
    int lane = threadIdx.x & 31;
    int chunk = lane & 15;
    int half = lane >> 4;

    const int* bucket = g_elist + (size_t)warp * CAP;

    // speculative idx prefetch: always in-bounds (bucket has CAP slots).
    // These issue in parallel with the g_cnt load below.
    int p0 = __ldg(bucket + half);
    int p1 = __ldg(bucket + half + 2);
    int p2 = __ldg(bucket + half + 4);
    int p3 = __ldg(bucket + half + 6);

    int deg_full = g_cnt[warp];
    int deg = deg_full > CAP ? CAP : deg_full;

    float4 a0 = make_float4(0.f, 0.f, 0.f, 0.f);
    float4 a1 = make_float4(0.f, 0.f, 0.f, 0.f);
    float4 a2 = make_float4(0.f, 0.f, 0.f, 0.f);
    float4 a3 = make_float4(0.f, 0.f, 0.f, 0.f);

    // first batch: edges half+0/2/4/6, gathers predicated on e < deg
    if (half < deg) {
        float4 v = __ldg(x4 + (size_t)p0 * CHUNKS + chunk);
        a0.x += v.x; a0.y += v.y; a0.z += v.z; a0.w += v.w;
    }
    if (half + 2 < deg) {
        float4 v = __ldg(x4 + (size_t)p1 * CHUNKS + chunk);
        a1.x += v.x; a1.y += v.y; a1.z += v.z; a1.w += v.w;
    }
    if (half + 4 < deg) {
        float4 v = __ldg(x4 + (size_t)p2 * CHUNKS + chunk);
        a2.x += v.x; a2.y += v.y; a2.z += v.z; a2.w += v.w;
    }
    if (half + 6 < deg) {
        float4 v = __ldg(x4 + (size_t)p3 * CHUNKS + chunk);
        a3.x += v.x; a3.y += v.y; a3.z += v.z; a3.w += v.w;
    }

    // tail: 2-wide strided loop
    int e = half + 8;
    for (; e < deg; e += 2) {
        int s = __ldg(bucket + e);
        float4 v = __ldg(x4 + (size_t)s * CHUNKS + chunk);
        a0.x += v.x; a0.y += v.y; a0.z += v.z; a0.w += v.w;
    }

    if (deg_full > CAP) {
        // astronomically rare: fold in this node's spill entries
        int novf = g_cnt[n_nodes];
        if (novf > MAX_OVF) novf = MAX_OVF;
        for (int i = half; i < novf; i += 2) {
            int2 sd = g_ovf[i];
            if (sd.y == warp) {
                float4 v = __ldg(x4 + (size_t)sd.x * CHUNKS + chunk);
                a0.x += v.x; a0.y += v.y; a0.z += v.z; a0.w += v.w;
            }
        }
    }

    // self-clean counters for the next graph replay
    if (lane == 0) g_cnt[warp] = 0;
    if (warp == 0 && lane == 1) g_cnt[n_nodes] = 0;

    a0.x += a1.x + a2.x + a3.x;
    a0.y += a1.y + a2.y + a3.y;
    a0.z += a1.z + a2.z + a3.z;
    a0.w += a1.w + a2.w + a3.w;

    a0.x += __shfl_down_sync(0xffffffffu, a0.x, 16);
    a0.y += __shfl_down_sync(0xffffffffu, a0.y, 16);
    a0.z += __shfl_down_sync(0xffffffffu, a0.z, 16);
    a0.w += __shfl_down_sync(0xffffffffu, a0.w, 16);

    if (half == 0) {
        out4[(size_t)warp * CHUNKS + chunk] = a0;
    }
}

// ---------------- fallback: proven atomic scatter (R4, 72us) ----------------

__global__ void scatter_add_kernel(const float4* __restrict__ x4,
                                   const int* __restrict__ src_idx,
                                   const int* __restrict__ dst_idx,
                                   float* __restrict__ out,
                                   int n_edges, int n_nodes)
{
    long long tid = (long long)blockIdx.x * blockDim.x + threadIdx.x;
    long long edge = tid >> 4;
    int chunk = (int)(tid & 15);
    if (edge >= n_edges) return;
    int s = __ldg(src_idx + edge);
    int d = __ldg(dst_idx + edge);
    if ((unsigned)s >= (unsigned)n_nodes || (unsigned)d >= (unsigned)n_nodes) return;
    float4 v = __ldg(x4 + (size_t)s * CHUNKS + chunk);
    float* dst_ptr = out + (size_t)d * D_FEAT + (size_t)chunk * 4;
    asm volatile("red.global.add.v4.f32 [%0], {%1, %2, %3, %4};"
                 :: "l"(dst_ptr), "f"(v.x), "f"(v.y), "f"(v.z), "f"(v.w)
                 : "memory");
}

extern "C" void kernel_launch(void* const* d_in, const int* in_sizes, int n_in,
                              void* d_out, int out_size)
{
    // Role detection by element count: x (6.4M fp32) > edge_index (2.5M int32)
    int xi = 0, ei = 1;
    if (n_in >= 2 && in_sizes[1] > in_sizes[0]) { xi = 1; ei = 0; }

    const float4* x4 = (const float4*)d_in[xi];
    const int* edge_index = (const int*)d_in[ei];

    int n_edges = in_sizes[ei] / 2;
    int n_nodes = in_sizes[xi] / D_FEAT;

    const int* src_idx = edge_index;            // row 0
    const int* dst_idx = edge_index + n_edges;  // row 1

    float* out = (float*)d_out;

    if (n_nodes > MAX_NODES || n_edges > MAX_EDGES) {
        cudaMemsetAsync(out, 0, (size_t)out_size * sizeof(float));
        long long total = (long long)n_edges * CHUNKS;
        scatter_add_kernel<<<(int)((total + 255) / 256), 256>>>(
            x4, src_idx, dst_idx, out, n_edges, n_nodes);
        return;
    }

    int Q = (n_edges + BU - 1) / BU;
    bucket_kernel<<<(Q + 255) / 256, 256>>>(src_idx, dst_idx,
                                            n_edges, n_nodes, Q);

    long long total = (long long)n_nodes * 32;
    aggregate_kernel<<<(int)((total + 255) / 256), 256>>>(x4, (float4*)d_out,
                                                          n_nodes);
}

// round 17
// speedup vs baseline: 1.1585x; 1.1585x over previous
#include <cuda_runtime.h>
#include <cstdint>

// Phase 1: bucket edges by dst (CAP/node), 8 edges/thread (MLP=8).
// Phase 2: warp-per-node gather-reduce (R15 measured-best form) plus a
//          MINIMAL 2-index speculative prefetch (costs 2 regs): the first two
//          bucket indices per half load before/parallel-with the g_cnt load,
//          removing the serial cnt->idx L2 link. Gathers stay predicated.
//          Rule from R13/R16: keep regs <= ~34, occupancy is the latency hiding.

#define D_FEAT 64
#define CHUNKS 16
#define CAP 64            // Poisson(12.5): P(deg>64) ~ 1e-24 per node
#define BU 8              // edges per bucket thread

#define MAX_NODES 131072
#define MAX_EDGES 2097152
#define MAX_OVF   4096

__device__ int g_cnt[MAX_NODES + 1];   // [n_nodes] = overflow counter; zero-init
__device__ int g_elist[MAX_NODES * CAP];
__device__ int2 g_ovf[MAX_OVF];        // (src, dst)

// ---------------- build buckets, 8 edges/thread ----------------

__global__ void bucket_kernel(const int* __restrict__ src,
                              const int* __restrict__ dst,
                              int n_edges, int n_nodes, int Q)
{
    int t = blockIdx.x * blockDim.x + threadIdx.x;
    if (t >= Q) return;

    int s[BU], d[BU], ok[BU];
#pragma unroll
    for (int k = 0; k < BU; k++) {
        int e = t + k * Q;
        ok[k] = (e < n_edges);
        if (ok[k]) {
            s[k] = __ldg(src + e);
            d[k] = __ldg(dst + e);
            if ((unsigned)s[k] >= (unsigned)n_nodes ||
                (unsigned)d[k] >= (unsigned)n_nodes) ok[k] = 0;
        }
    }

    int pos[BU];
#pragma unroll
    for (int k = 0; k < BU; k++)
        if (ok[k]) pos[k] = atomicAdd(&g_cnt[d[k]], 1);

#pragma unroll
    for (int k = 0; k < BU; k++) {
        if (!ok[k]) continue;
        if (pos[k] < CAP) {
            g_elist[(size_t)d[k] * CAP + pos[k]] = s[k];
        } else {
            int op = atomicAdd(&g_cnt[n_nodes], 1);
            if (op < MAX_OVF) g_ovf[op] = make_int2(s[k], d[k]);
        }
    }
}

// ---------------- warp-per-node gather-reduce ----------------
// lane = 2 halves (edge-parallel) x 16 chunks; fold halves with 4 shfls;
// half 0 writes the row with ONE plain vector store.

__global__ void aggregate_kernel(const float4* __restrict__ x4,
                                 float4* __restrict__ out4,
                                 int n_nodes)
{
    int warp = (blockIdx.x * blockDim.x + threadIdx.x) >> 5;
    if (warp >= n_nodes) return;
    int lane = threadIdx.x & 31;
    int chunk = lane & 15;
    int half = lane >> 4;

    const int* bucket = g_elist + (size_t)warp * CAP;

    // minimal speculative prefetch: first two indices per half, always
    // in-bounds (bucket has CAP slots); overlaps the g_cnt load below.
    int p0 = __ldg(bucket + half);
    int p1 = __ldg(bucket + half + 2);

    int deg_full = g_cnt[warp];
    int deg = deg_full > CAP ? CAP : deg_full;

    float4 a = make_float4(0.f, 0.f, 0.f, 0.f);

    if (half < deg) {
        float4 v = __ldg(x4 + (size_t)p0 * CHUNKS + chunk);
        a.x += v.x; a.y += v.y; a.z += v.z; a.w += v.w;
    }
    if (half + 2 < deg) {
        float4 v = __ldg(x4 + (size_t)p1 * CHUNKS + chunk);
        a.x += v.x; a.y += v.y; a.z += v.z; a.w += v.w;
    }

#pragma unroll 2
    for (int e = half + 4; e < deg; e += 2) {
        int s = __ldg(bucket + e);
        float4 v = __ldg(x4 + (size_t)s * CHUNKS + chunk);
        a.x += v.x; a.y += v.y; a.z += v.z; a.w += v.w;
    }

    if (deg_full > CAP) {
        // astronomically rare: fold in this node's spill entries
        int novf = g_cnt[n_nodes];
        if (novf > MAX_OVF) novf = MAX_OVF;
        for (int i = half; i < novf; i += 2) {
            int2 sd = g_ovf[i];
            if (sd.y == warp) {
                float4 v = __ldg(x4 + (size_t)sd.x * CHUNKS + chunk);
                a.x += v.x; a.y += v.y; a.z += v.z; a.w += v.w;
            }
        }
    }

    // self-clean counters for the next graph replay (write-after-read)
    if (lane == 0) g_cnt[warp] = 0;
    if (warp == 0 && lane == 1) g_cnt[n_nodes] = 0;

    a.x += __shfl_down_sync(0xffffffffu, a.x, 16);
    a.y += __shfl_down_sync(0xffffffffu, a.y, 16);
    a.z += __shfl_down_sync(0xffffffffu, a.z, 16);
    a.w += __shfl_down_sync(0xffffffffu, a.w, 16);

    if (half == 0) {
        out4[(size_t)warp * CHUNKS + chunk] = a;
    }
}

// ---------------- fallback: proven atomic scatter (R4, 72us) ----------------

__global__ void scatter_add_kernel(const float4* __restrict__ x4,
                                   const int* __restrict__ src_idx,
                                   const int* __restrict__ dst_idx,
                                   float* __restrict__ out,
                                   int n_edges, int n_nodes)
{
    long long tid = (long long)blockIdx.x * blockDim.x + threadIdx.x;
    long long edge = tid >> 4;
    int chunk = (int)(tid & 15);
    if (edge >= n_edges) return;
    int s = __ldg(src_idx + edge);
    int d = __ldg(dst_idx + edge);
    if ((unsigned)s >= (unsigned)n_nodes || (unsigned)d >= (unsigned)n_nodes) return;
    float4 v = __ldg(x4 + (size_t)s * CHUNKS + chunk);
    float* dst_ptr = out + (size_t)d * D_FEAT + (size_t)chunk * 4;
    asm volatile("red.global.add.v4.f32 [%0], {%1, %2, %3, %4};"
                 :: "l"(dst_ptr), "f"(v.x), "f"(v.y), "f"(v.z), "f"(v.w)
                 : "memory");
}

extern "C" void kernel_launch(void* const* d_in, const int* in_sizes, int n_in,
                              void* d_out, int out_size)
{
    // Role detection by element count: x (6.4M fp32) > edge_index (2.5M int32)
    int xi = 0, ei = 1;
    if (n_in >= 2 && in_sizes[1] > in_sizes[0]) { xi = 1; ei = 0; }

    const float4* x4 = (const float4*)d_in[xi];
    const int* edge_index = (const int*)d_in[ei];

    int n_edges = in_sizes[ei] / 2;
    int n_nodes = in_sizes[xi] / D_FEAT;

    const int* src_idx = edge_index;            // row 0
    const int* dst_idx = edge_index + n_edges;  // row 1

    float* out = (float*)d_out;

    if (n_nodes > MAX_NODES || n_edges > MAX_EDGES) {
        cudaMemsetAsync(out, 0, (size_t)out_size * sizeof(float));
        long long total = (long long)n_edges * CHUNKS;
        scatter_add_kernel<<<(int)((total + 255) / 256), 256>>>(
            x4, src_idx, dst_idx, out, n_edges, n_nodes);
        return;
    }

    int Q = (n_edges + BU - 1) / BU;
    bucket_kernel<<<(Q + 255) / 256, 256>>>(src_idx, dst_idx,
                                            n_edges, n_nodes, Q);

    long long total = (long long)n_nodes * 32;
    aggregate_kernel<<<(int)((total + 255) / 256), 256>>>(x4, (float4*)d_out,
                                                          n_nodes);
}